// round 6
// baseline (speedup 1.0000x reference)
#include <cuda_runtime.h>
#include <cstdint>
#include <cstddef>

// Problem constants
#define BB    4
#define CIN   256
#define HH    56
#define WW    56
#define COUT  256
#define KK9   9
#define OCH   18
#define P     (HH*WW)     // 3136
#define NTOT  (BB*P)      // 12544
#define KDIM  (CIN*KK9)   // 2304

#define NCHUNK 16
#define CCH    (CIN/NCHUNK)   // 16

// GEMM tiling (tf32)
#define BM   128
#define BN   64
#define BK   16
#define NKC  (KDIM/BK)    // 144
#define NSTAGE 3

// smem geometry (bytes)
#define A_ROWB 80                     // 16 fp32 = 64B + 16B pad (ldmatrix conflict-free)
#define B_ROWB 288                    // 64 fp32 = 256B + 32B pad (LDS conflict-free: 72w ≡ 8 mod 32)
#define A_PLANE (BM*A_ROWB)           // 10240
#define B_OFF   A_PLANE
#define B_PLANE (BK*B_ROWB)           // 4608
#define BUF_BYTES (A_PLANE+B_PLANE)   // 14848
#define SMEM_TOTAL (NSTAGE*BUF_BYTES) // 44544

// offconv strips
#define SY_N  (HH/4)
#define STRIPS (BB*SY_N*WW)

// Scratch (device globals)
__device__ __align__(16) float g_OffP[NCHUNK * BB * OCH * P];
__device__ __align__(16) float g_St[(size_t)KDIM * NTOT];   // tf32-rounded samples
__device__ __align__(16) float g_Wt[COUT * KDIM];           // tf32-rounded weights

// ---------------------------------------------------------------------------
// helpers
// ---------------------------------------------------------------------------
__device__ __forceinline__ uint32_t smem_u32(const void* p) {
    uint32_t a;
    asm("{ .reg .u64 t; cvta.to.shared.u64 t, %1; cvt.u32.u64 %0, t; }" : "=r"(a) : "l"(p));
    return a;
}
__device__ __forceinline__ float to_tf32(float v) {
    uint32_t r;
    asm("cvt.rna.tf32.f32 %0, %1;" : "=r"(r) : "f"(v));
    return __uint_as_float(r);
}
__device__ __forceinline__ void cp16(uint32_t dst, const void* src) {
    asm volatile("cp.async.ca.shared.global [%0], [%1], 16;" :: "r"(dst), "l"(src) : "memory");
}
__device__ __forceinline__ void cp_commit() {
    asm volatile("cp.async.commit_group;" ::: "memory");
}
__device__ __forceinline__ void cp_wait1() {
    asm volatile("cp.async.wait_group 1;" ::: "memory");
}
__device__ __forceinline__ void ldsm_x4(uint32_t* r, uint32_t addr) {
    asm volatile("ldmatrix.sync.aligned.m8n8.x4.shared.b16 {%0,%1,%2,%3}, [%4];"
                 : "=r"(r[0]), "=r"(r[1]), "=r"(r[2]), "=r"(r[3]) : "r"(addr));
}
__device__ __forceinline__ void mma_tf32(float* c, const uint32_t* a, uint32_t b0, uint32_t b1) {
    asm volatile("mma.sync.aligned.m16n8k8.row.col.f32.tf32.tf32.f32 "
                 "{%0,%1,%2,%3}, {%4,%5,%6,%7}, {%8,%9}, {%0,%1,%2,%3};"
                 : "+f"(c[0]), "+f"(c[1]), "+f"(c[2]), "+f"(c[3])
                 : "r"(a[0]), "r"(a[1]), "r"(a[2]), "r"(a[3]), "r"(b0), "r"(b1));
}

// ---------------------------------------------------------------------------
// Kernel 0: weight -> tf32-rounded fp32
// ---------------------------------------------------------------------------
__global__ __launch_bounds__(256) void wcvt_kernel(const float* __restrict__ w) {
    int i = blockIdx.x * 256 + threadIdx.x;
    if (i >= COUT * KDIM) return;
    g_Wt[i] = to_tf32(w[i]);
}

// ---------------------------------------------------------------------------
// Kernel 1: offset conv, 4-row strips (round-5 version, verified)
// ---------------------------------------------------------------------------
__global__ __launch_bounds__(256) void offconv_kernel(
    const float* __restrict__ x, const float* __restrict__ off_w,
    const float* __restrict__ off_b)
{
    __shared__ __align__(16) float ws[OCH * CCH * KK9];
    const int tid   = threadIdx.x;
    const int chunk = blockIdx.y;
    const int ci0   = chunk * CCH;

    for (int i = tid; i < OCH * CCH * KK9; i += 256) {
        int oc  = i / (CCH * KK9);
        int rem = i % (CCH * KK9);
        int cl  = rem / KK9;
        int t   = rem % KK9;
        ws[i] = off_w[((size_t)(oc * CIN + ci0 + cl)) * KK9 + t];
    }
    __syncthreads();

    const int id = blockIdx.x * 256 + tid;
    if (id >= STRIPS) return;
    const int b   = id / (SY_N * WW);
    const int s   = id % (SY_N * WW);
    const int sy  = s / WW;
    const int sx  = s % WW;
    const int y0r = sy * 4;

    float acc[OCH][4];
#pragma unroll
    for (int oc = 0; oc < OCH; oc++) {
        float bias = (chunk == 0) ? off_b[oc] : 0.0f;
#pragma unroll
        for (int r = 0; r < 4; r++) acc[oc][r] = bias;
    }

    const float* xb = x + ((size_t)(b * CIN + ci0)) * P;
    for (int cl = 0; cl < CCH; cl++) {
        const float* xc = xb + (size_t)cl * P;
        float v[6][3];
#pragma unroll
        for (int dy = 0; dy < 6; dy++) {
            int y = y0r - 1 + dy;
#pragma unroll
            for (int dx = 0; dx < 3; dx++) {
                int xx = sx - 1 + dx;
                v[dy][dx] = (y >= 0 && y < HH && xx >= 0 && xx < WW)
                          ? xc[y * WW + xx] : 0.0f;
            }
        }
        const float* wsc = ws + cl * KK9;
#pragma unroll
        for (int oc = 0; oc < OCH; oc++) {
            const float* wo = wsc + oc * (CCH * KK9);
#pragma unroll
            for (int t = 0; t < KK9; t++) {
                float w = wo[t];
                int ty = t / 3, tx = t % 3;
#pragma unroll
                for (int r = 0; r < 4; r++)
                    acc[oc][r] = fmaf(v[r + ty][tx], w, acc[oc][r]);
            }
        }
    }

    float* op = g_OffP + (((size_t)chunk * BB + b) * OCH) * P;
#pragma unroll
    for (int oc = 0; oc < OCH; oc++) {
#pragma unroll
        for (int r = 0; r < 4; r++)
            op[(size_t)oc * P + (y0r + r) * WW + sx] = acc[oc][r];
    }
}

// ---------------------------------------------------------------------------
// Kernel 2: bilinear sampling -> tf32-rounded fp32 S[k=ci*9+kk][n=b*P+p]
// ---------------------------------------------------------------------------
__global__ __launch_bounds__(256) void sample_kernel(const float* __restrict__ x)
{
    const int tid = threadIdx.x;
    const int p   = blockIdx.x * 256 + tid;
    if (p >= P) return;
    const int b  = blockIdx.y;
    const int kk = blockIdx.z;

    float offy = 0.0f, offx = 0.0f;
#pragma unroll
    for (int c = 0; c < NCHUNK; c++) {
        const float* op = g_OffP + (((size_t)c * BB + b) * OCH + 2 * kk) * P + p;
        offy += op[0];
        offx += op[P];
    }

    const int ho = p / WW;
    const int wo = p % WW;
    const float py = (float)(ho - 1 + kk / 3) + offy;
    const float px = (float)(wo - 1 + kk % 3) + offx;
    const float fy = floorf(py), fx = floorf(px);
    const int y0 = (int)fy, x0 = (int)fx;
    const int y1 = y0 + 1,  x1 = x0 + 1;
    const float ty = py - fy, tx = px - fx;

    float w00 = (1.0f - ty) * (1.0f - tx);
    float w01 = (1.0f - ty) * tx;
    float w10 = ty * (1.0f - tx);
    float w11 = ty * tx;

    const bool vy0 = (y0 >= 0 && y0 < HH), vy1 = (y1 >= 0 && y1 < HH);
    const bool vx0 = (x0 >= 0 && x0 < WW), vx1 = (x1 >= 0 && x1 < WW);
    w00 *= (vy0 && vx0) ? 1.0f : 0.0f;
    w01 *= (vy0 && vx1) ? 1.0f : 0.0f;
    w10 *= (vy1 && vx0) ? 1.0f : 0.0f;
    w11 *= (vy1 && vx1) ? 1.0f : 0.0f;

    const int cy0 = min(max(y0, 0), HH - 1), cy1 = min(max(y1, 0), HH - 1);
    const int cx0 = min(max(x0, 0), WW - 1), cx1 = min(max(x1, 0), WW - 1);
    const int i00 = cy0 * WW + cx0, i01 = cy0 * WW + cx1;
    const int i10 = cy1 * WW + cx0, i11 = cy1 * WW + cx1;

    const float* xb = x + (size_t)b * CIN * P;
    const size_t base = (size_t)kk * NTOT + (size_t)b * P + p;
    const size_t srow = (size_t)KK9 * NTOT;

#pragma unroll 4
    for (int ci = 0; ci < CIN; ci++) {
        const float* xc = xb + (size_t)ci * P;
        float v = w00 * __ldg(xc + i00) + w01 * __ldg(xc + i01)
                + w10 * __ldg(xc + i10) + w11 * __ldg(xc + i11);
        g_St[base + (size_t)ci * srow] = to_tf32(v);
    }
}

// ---------------------------------------------------------------------------
// Kernel 3: tf32 single-pass mma.sync GEMM.
// BM=128, BN=64, BK=16; 8 warps 4(M)x2(N), warp tile 32x32.
// ---------------------------------------------------------------------------
__device__ __forceinline__ void prefetch_chunk(uint32_t sbase, int tid,
                                               int m0, int n0, int k0)
{
    // A: 128 rows x 4 chunks of 16B (512 cp16)
#pragma unroll
    for (int it = 0; it < 2; it++) {
        int idx = it * 256 + tid;
        int row = idx >> 2;
        int c   = idx & 3;
        cp16(sbase + row * A_ROWB + c * 16,
             g_Wt + (size_t)(m0 + row) * KDIM + k0 + c * 4);
    }
    // B: 16 rows x 16 chunks of 16B (256 cp16)
    {
        int row = tid >> 4;
        int c   = tid & 15;
        cp16(sbase + B_OFF + row * B_ROWB + c * 16,
             g_St + (size_t)(k0 + row) * NTOT + n0 + c * 4);
    }
}

__global__ __launch_bounds__(256, 3) void gemm_mma_kernel(float* __restrict__ out)
{
    extern __shared__ char smem[];
    const uint32_t sb = smem_u32(smem);
    const int tid  = threadIdx.x;
    const int wid  = tid >> 5;
    const int lane = tid & 31;
    const int wm   = wid & 3;
    const int wn   = wid >> 2;
    const int n0   = blockIdx.x * BN;
    const int m0   = blockIdx.y * BM;

    float acc[2][4][4];
#pragma unroll
    for (int i = 0; i < 2; i++)
#pragma unroll
        for (int j = 0; j < 4; j++)
#pragma unroll
            for (int q = 0; q < 4; q++) acc[i][j][q] = 0.0f;

    // A ldmatrix per-thread base: tile t/8 of m16k8 region
    const int arow  = (lane & 7) + ((lane >> 3) & 1) * 8;   // row within m16
    const int aqcol = lane >> 4;                            // 0/1 -> +16B (cols 4-7)
    const uint32_t a_base = (uint32_t)(wm * 32 + arow) * A_ROWB + aqcol * 16;
    // B scalar-LDS per-thread base: k = lane%4, n = wn*32 + lane/4
    const uint32_t b_base = B_OFF + (uint32_t)(lane & 3) * B_ROWB
                          + (uint32_t)(wn * 32 + (lane >> 2)) * 4;

    prefetch_chunk(sb, tid, m0, n0, 0);
    cp_commit();
    prefetch_chunk(sb + BUF_BYTES, tid, m0, n0, BK);
    cp_commit();

    for (int kc = 0; kc < NKC; kc++) {
        cp_wait1();
        __syncthreads();
        if (kc + 2 < NKC)
            prefetch_chunk(sb + (uint32_t)((kc + 2) % NSTAGE) * BUF_BYTES,
                           tid, m0, n0, (kc + 2) * BK);
        cp_commit();

        const uint32_t buf = sb + (uint32_t)(kc % NSTAGE) * BUF_BYTES;
#pragma unroll
        for (int kk = 0; kk < 2; kk++) {   // two k8 steps per chunk
            uint32_t A[2][4];
#pragma unroll
            for (int mt = 0; mt < 2; mt++)
                ldsm_x4(A[mt], buf + a_base + (uint32_t)mt * 16 * A_ROWB + kk * 32);

            uint32_t B0[4], B1[4];
            const uint32_t bb = buf + b_base + (uint32_t)kk * 8 * B_ROWB;
#pragma unroll
            for (int nt = 0; nt < 4; nt++) {
                asm volatile("ld.shared.b32 %0, [%1];" : "=r"(B0[nt]) : "r"(bb + nt * 32));
                asm volatile("ld.shared.b32 %0, [%1];" : "=r"(B1[nt]) : "r"(bb + nt * 32 + 4 * B_ROWB));
            }
#pragma unroll
            for (int mt = 0; mt < 2; mt++)
#pragma unroll
                for (int nt = 0; nt < 4; nt++)
                    mma_tf32(acc[mt][nt], A[mt], B0[nt], B1[nt]);
        }
    }

    const int g = lane >> 2;
    const int t = lane & 3;
    const int bidx = n0 / P;
    const int pofs = n0 % P;
#pragma unroll
    for (int mt = 0; mt < 2; mt++) {
        int mrow = m0 + wm * 32 + mt * 16 + g;
        float* r0 = out + ((size_t)(bidx * COUT + mrow)) * P + pofs;
        float* r1 = r0 + 8 * P;
#pragma unroll
        for (int nt = 0; nt < 4; nt++) {
            int col = wn * 32 + nt * 8 + 2 * t;
            *(float2*)(r0 + col) = make_float2(acc[mt][nt][0], acc[mt][nt][1]);
            *(float2*)(r1 + col) = make_float2(acc[mt][nt][2], acc[mt][nt][3]);
        }
    }
}

// ---------------------------------------------------------------------------
extern "C" void kernel_launch(void* const* d_in, const int* in_sizes, int n_in,
                              void* d_out, int out_size)
{
    const float* x     = (const float*)d_in[0];
    const float* wgt   = (const float*)d_in[1];
    const float* off_w = (const float*)d_in[2];
    const float* off_b = (const float*)d_in[3];
    float* out = (float*)d_out;

    cudaFuncSetAttribute(gemm_mma_kernel, cudaFuncAttributeMaxDynamicSharedMemorySize, SMEM_TOTAL);

    wcvt_kernel<<<(COUT * KDIM + 255) / 256, 256>>>(wgt);

    dim3 g1((STRIPS + 255) / 256, NCHUNK);
    offconv_kernel<<<g1, 256>>>(x, off_w, off_b);

    dim3 g2((P + 255) / 256, BB, KK9);
    sample_kernel<<<g2, 256>>>(x);

    dim3 g3(NTOT / BN, COUT / BM);
    gemm_mma_kernel<<<g3, 256, SMEM_TOTAL>>>(out);
}

// round 7
// speedup vs baseline: 1.5014x; 1.5014x over previous
#include <cuda_runtime.h>
#include <cuda_bf16.h>
#include <cstdint>
#include <cstddef>

// Problem constants
#define BB    4
#define CIN   256
#define HH    56
#define WW    56
#define COUT  256
#define KK9   9
#define OCH   18
#define P     (HH*WW)     // 3136
#define NTOT  (BB*P)      // 12544
#define KDIM  (CIN*KK9)   // 2304

#define NCHUNK 16
#define CCH    (CIN/NCHUNK)   // 16

// GEMM tiling (bf16 split, 3 passes)
#define BM   128
#define BN   64
#define BK   32
#define NKC  (KDIM/BK)    // 72

// padded smem rows (bytes)
#define A_ROWB 80
#define B_ROWB 144
#define A_PLANE (BM*A_ROWB)
#define B_PLANE (BK*B_ROWB)
#define A_LO_OFF A_PLANE
#define B_HI_OFF (2*A_PLANE)
#define B_LO_OFF (2*A_PLANE+B_PLANE)
#define BUF_BYTES (2*A_PLANE+2*B_PLANE)   // 29696
#define SMEM_TOTAL (2*BUF_BYTES)          // 59392 -> 3 CTAs/SM smem-wise

// offconv strips
#define SY_N  (HH/4)
#define STRIPS (BB*SY_N*WW)

// Scratch (device globals)
__device__ __align__(16) float g_OffP[NCHUNK * BB * OCH * P];
__device__ __align__(16) __nv_bfloat16 g_Shi[(size_t)KDIM * NTOT];
__device__ __align__(16) __nv_bfloat16 g_Slo[(size_t)KDIM * NTOT];
__device__ __align__(16) __nv_bfloat16 g_Whi[COUT * KDIM];
__device__ __align__(16) __nv_bfloat16 g_Wlo[COUT * KDIM];

// ---------------------------------------------------------------------------
// helpers
// ---------------------------------------------------------------------------
__device__ __forceinline__ uint32_t smem_u32(const void* p) {
    uint32_t a;
    asm("{ .reg .u64 t; cvta.to.shared.u64 t, %1; cvt.u32.u64 %0, t; }" : "=r"(a) : "l"(p));
    return a;
}
__device__ __forceinline__ void cp16(uint32_t dst, const void* src) {
    asm volatile("cp.async.ca.shared.global [%0], [%1], 16;" :: "r"(dst), "l"(src) : "memory");
}
__device__ __forceinline__ void cp_commit() {
    asm volatile("cp.async.commit_group;" ::: "memory");
}
__device__ __forceinline__ void cp_wait1() {
    asm volatile("cp.async.wait_group 1;" ::: "memory");
}
__device__ __forceinline__ void cp_wait0() {
    asm volatile("cp.async.wait_group 0;" ::: "memory");
}
__device__ __forceinline__ void ldsm_x4(uint32_t* r, uint32_t addr) {
    asm volatile("ldmatrix.sync.aligned.m8n8.x4.shared.b16 {%0,%1,%2,%3}, [%4];"
                 : "=r"(r[0]), "=r"(r[1]), "=r"(r[2]), "=r"(r[3]) : "r"(addr));
}
__device__ __forceinline__ void ldsm_x4t(uint32_t* r, uint32_t addr) {
    asm volatile("ldmatrix.sync.aligned.m8n8.x4.trans.shared.b16 {%0,%1,%2,%3}, [%4];"
                 : "=r"(r[0]), "=r"(r[1]), "=r"(r[2]), "=r"(r[3]) : "r"(addr));
}
__device__ __forceinline__ void mma_bf16(float* c, const uint32_t* a, uint32_t b0, uint32_t b1) {
    asm volatile("mma.sync.aligned.m16n8k16.row.col.f32.bf16.bf16.f32 "
                 "{%0,%1,%2,%3}, {%4,%5,%6,%7}, {%8,%9}, {%0,%1,%2,%3};"
                 : "+f"(c[0]), "+f"(c[1]), "+f"(c[2]), "+f"(c[3])
                 : "r"(a[0]), "r"(a[1]), "r"(a[2]), "r"(a[3]), "r"(b0), "r"(b1));
}

// ---------------------------------------------------------------------------
// Kernel 0: weight -> bf16 hi/lo split
// ---------------------------------------------------------------------------
__global__ __launch_bounds__(256) void wconv_kernel(const float* __restrict__ w) {
    int i = blockIdx.x * 256 + threadIdx.x;
    if (i >= COUT * KDIM) return;
    float v = w[i];
    __nv_bfloat16 hi = __float2bfloat16_rn(v);
    __nv_bfloat16 lo = __float2bfloat16_rn(v - __bfloat162float(hi));
    g_Whi[i] = hi;
    g_Wlo[i] = lo;
}

// ---------------------------------------------------------------------------
// Kernel 1: offset conv, 4-row strips (round-5, verified)
// ---------------------------------------------------------------------------
__global__ __launch_bounds__(256) void offconv_kernel(
    const float* __restrict__ x, const float* __restrict__ off_w,
    const float* __restrict__ off_b)
{
    __shared__ __align__(16) float ws[OCH * CCH * KK9];
    const int tid   = threadIdx.x;
    const int chunk = blockIdx.y;
    const int ci0   = chunk * CCH;

    for (int i = tid; i < OCH * CCH * KK9; i += 256) {
        int oc  = i / (CCH * KK9);
        int rem = i % (CCH * KK9);
        int cl  = rem / KK9;
        int t   = rem % KK9;
        ws[i] = off_w[((size_t)(oc * CIN + ci0 + cl)) * KK9 + t];
    }
    __syncthreads();

    const int id = blockIdx.x * 256 + tid;
    if (id >= STRIPS) return;
    const int b   = id / (SY_N * WW);
    const int s   = id % (SY_N * WW);
    const int sy  = s / WW;
    const int sx  = s % WW;
    const int y0r = sy * 4;

    float acc[OCH][4];
#pragma unroll
    for (int oc = 0; oc < OCH; oc++) {
        float bias = (chunk == 0) ? off_b[oc] : 0.0f;
#pragma unroll
        for (int r = 0; r < 4; r++) acc[oc][r] = bias;
    }

    const float* xb = x + ((size_t)(b * CIN + ci0)) * P;
    for (int cl = 0; cl < CCH; cl++) {
        const float* xc = xb + (size_t)cl * P;
        float v[6][3];
#pragma unroll
        for (int dy = 0; dy < 6; dy++) {
            int y = y0r - 1 + dy;
#pragma unroll
            for (int dx = 0; dx < 3; dx++) {
                int xx = sx - 1 + dx;
                v[dy][dx] = (y >= 0 && y < HH && xx >= 0 && xx < WW)
                          ? xc[y * WW + xx] : 0.0f;
            }
        }
        const float* wsc = ws + cl * KK9;
#pragma unroll
        for (int oc = 0; oc < OCH; oc++) {
            const float* wo = wsc + oc * (CCH * KK9);
#pragma unroll
            for (int t = 0; t < KK9; t++) {
                float w = wo[t];
                int ty = t / 3, tx = t % 3;
#pragma unroll
                for (int r = 0; r < 4; r++)
                    acc[oc][r] = fmaf(v[r + ty][tx], w, acc[oc][r]);
            }
        }
    }

    float* op = g_OffP + (((size_t)chunk * BB + b) * OCH) * P;
#pragma unroll
    for (int oc = 0; oc < OCH; oc++) {
#pragma unroll
        for (int r = 0; r < 4; r++)
            op[(size_t)oc * P + (y0r + r) * WW + sx] = acc[oc][r];
    }
}

// ---------------------------------------------------------------------------
// Kernel 2: bilinear sampling -> S hi/lo bf16, layout [k=ci*9+kk][n=b*P+p]
// ---------------------------------------------------------------------------
__global__ __launch_bounds__(256) void sample_kernel(const float* __restrict__ x)
{
    const int tid = threadIdx.x;
    const int p   = blockIdx.x * 256 + tid;
    if (p >= P) return;
    const int b  = blockIdx.y;
    const int kk = blockIdx.z;

    float offy = 0.0f, offx = 0.0f;
#pragma unroll
    for (int c = 0; c < NCHUNK; c++) {
        const float* op = g_OffP + (((size_t)c * BB + b) * OCH + 2 * kk) * P + p;
        offy += op[0];
        offx += op[P];
    }

    const int ho = p / WW;
    const int wo = p % WW;
    const float py = (float)(ho - 1 + kk / 3) + offy;
    const float px = (float)(wo - 1 + kk % 3) + offx;
    const float fy = floorf(py), fx = floorf(px);
    const int y0 = (int)fy, x0 = (int)fx;
    const int y1 = y0 + 1,  x1 = x0 + 1;
    const float ty = py - fy, tx = px - fx;

    float w00 = (1.0f - ty) * (1.0f - tx);
    float w01 = (1.0f - ty) * tx;
    float w10 = ty * (1.0f - tx);
    float w11 = ty * tx;

    const bool vy0 = (y0 >= 0 && y0 < HH), vy1 = (y1 >= 0 && y1 < HH);
    const bool vx0 = (x0 >= 0 && x0 < WW), vx1 = (x1 >= 0 && x1 < WW);
    w00 *= (vy0 && vx0) ? 1.0f : 0.0f;
    w01 *= (vy0 && vx1) ? 1.0f : 0.0f;
    w10 *= (vy1 && vx0) ? 1.0f : 0.0f;
    w11 *= (vy1 && vx1) ? 1.0f : 0.0f;

    const int cy0 = min(max(y0, 0), HH - 1), cy1 = min(max(y1, 0), HH - 1);
    const int cx0 = min(max(x0, 0), WW - 1), cx1 = min(max(x1, 0), WW - 1);
    const int i00 = cy0 * WW + cx0, i01 = cy0 * WW + cx1;
    const int i10 = cy1 * WW + cx0, i11 = cy1 * WW + cx1;

    const float* xb = x + (size_t)b * CIN * P;
    const size_t base = (size_t)kk * NTOT + (size_t)b * P + p;
    const size_t srow = (size_t)KK9 * NTOT;

#pragma unroll 4
    for (int ci = 0; ci < CIN; ci++) {
        const float* xc = xb + (size_t)ci * P;
        float v = w00 * __ldg(xc + i00) + w01 * __ldg(xc + i01)
                + w10 * __ldg(xc + i10) + w11 * __ldg(xc + i11);
        __nv_bfloat16 hi = __float2bfloat16_rn(v);
        __nv_bfloat16 lo = __float2bfloat16_rn(v - __bfloat162float(hi));
        g_Shi[base + (size_t)ci * srow] = hi;
        g_Slo[base + (size_t)ci * srow] = lo;
    }
}

// ---------------------------------------------------------------------------
// Kernel 3: mma.sync bf16-split GEMM, 2-stage pipeline (round-4 structure),
// running prefetch pointers, __launch_bounds__(256,3) for 3 CTAs/SM.
// ---------------------------------------------------------------------------
__global__ __launch_bounds__(256, 3) void gemm_mma_kernel(float* __restrict__ out)
{
    extern __shared__ char smem[];
    const uint32_t sb = smem_u32(smem);
    const int tid  = threadIdx.x;
    const int wid  = tid >> 5;
    const int lane = tid & 31;
    const int wm   = wid & 3;
    const int wn   = wid >> 2;
    const int n0   = blockIdx.x * BN;
    const int m0   = blockIdx.y * BM;

    float acc[2][4][4];
#pragma unroll
    for (int i = 0; i < 2; i++)
#pragma unroll
        for (int j = 0; j < 4; j++)
#pragma unroll
            for (int q = 0; q < 4; q++) acc[i][j][q] = 0.0f;

    // --- prefetch assignments (fixed per thread), running pointers ---
    const int ar0 = tid >> 2,           ac0 = tid & 3;          // A rows 0..63
    const int ar1 = (256 + tid) >> 2,   ac1 = (256 + tid) & 3;  // A rows 64..127
    const int br  = tid >> 3,           bc  = tid & 7;          // B rows 0..31
    const __nv_bfloat16* pAh0 = g_Whi + (size_t)(m0 + ar0) * KDIM + ac0 * 8;
    const __nv_bfloat16* pAl0 = g_Wlo + (size_t)(m0 + ar0) * KDIM + ac0 * 8;
    const __nv_bfloat16* pAh1 = g_Whi + (size_t)(m0 + ar1) * KDIM + ac1 * 8;
    const __nv_bfloat16* pAl1 = g_Wlo + (size_t)(m0 + ar1) * KDIM + ac1 * 8;
    const __nv_bfloat16* pBh  = g_Shi + (size_t)br * NTOT + n0 + bc * 8;
    const __nv_bfloat16* pBl  = g_Slo + (size_t)br * NTOT + n0 + bc * 8;
    const uint32_t dA0 = ar0 * A_ROWB + ac0 * 16;
    const uint32_t dA1 = ar1 * A_ROWB + ac1 * 16;
    const uint32_t dB  = br * B_ROWB + bc * 16;

    // ldmatrix per-thread address components
    const int lrow  = lane & 15;
    const int lhalf = lane >> 4;
    const uint32_t a_row_off = (uint32_t)(wm * 32 + lrow) * A_ROWB + lhalf * 16;
    const uint32_t b_off = (uint32_t)lrow * B_ROWB + (uint32_t)(wn * 32 + lhalf * 8) * 2;

    // preload chunk 0 into stage 0
    {
        const uint32_t s0 = sb;
        cp16(s0 + dA0, pAh0);                 cp16(s0 + A_LO_OFF + dA0, pAl0);
        cp16(s0 + dA1, pAh1);                 cp16(s0 + A_LO_OFF + dA1, pAl1);
        cp16(s0 + B_HI_OFF + dB, pBh);        cp16(s0 + B_LO_OFF + dB, pBl);
        pAh0 += BK; pAl0 += BK; pAh1 += BK; pAl1 += BK;
        pBh += (size_t)BK * NTOT; pBl += (size_t)BK * NTOT;
    }
    cp_commit();

#pragma unroll 1
    for (int kc = 0; kc < NKC; kc++) {
        const uint32_t buf = sb + (uint32_t)(kc & 1) * BUF_BYTES;
        if (kc < NKC - 1) {
            const uint32_t nb = sb + (uint32_t)((kc + 1) & 1) * BUF_BYTES;
            cp16(nb + dA0, pAh0);             cp16(nb + A_LO_OFF + dA0, pAl0);
            cp16(nb + dA1, pAh1);             cp16(nb + A_LO_OFF + dA1, pAl1);
            cp16(nb + B_HI_OFF + dB, pBh);    cp16(nb + B_LO_OFF + dB, pBl);
            pAh0 += BK; pAl0 += BK; pAh1 += BK; pAl1 += BK;
            pBh += (size_t)BK * NTOT; pBl += (size_t)BK * NTOT;
            cp_commit();
            cp_wait1();
        } else {
            cp_wait0();
        }
        __syncthreads();

#pragma unroll
        for (int kk = 0; kk < 2; kk++) {
            uint32_t Ah[2][4], Al[2][4], Bh[2][4], Bl[2][4];
#pragma unroll
            for (int mt = 0; mt < 2; mt++) {
                uint32_t aaddr = buf + a_row_off + (uint32_t)mt * 16 * A_ROWB + kk * 32;
                ldsm_x4(Ah[mt], aaddr);
                ldsm_x4(Al[mt], aaddr + A_LO_OFF);
            }
#pragma unroll
            for (int bq = 0; bq < 2; bq++) {
                uint32_t baddr = buf + B_HI_OFF + b_off + (uint32_t)kk * 16 * B_ROWB + bq * 32;
                ldsm_x4t(Bh[bq], baddr);
                ldsm_x4t(Bl[bq], baddr + (B_LO_OFF - B_HI_OFF));
            }
#pragma unroll
            for (int mt = 0; mt < 2; mt++) {
#pragma unroll
                for (int bq = 0; bq < 2; bq++) {
#pragma unroll
                    for (int h = 0; h < 2; h++) {
                        int nt = bq * 2 + h;
                        mma_bf16(acc[mt][nt], Ah[mt], Bh[bq][2*h], Bh[bq][2*h+1]);
                        mma_bf16(acc[mt][nt], Ah[mt], Bl[bq][2*h], Bl[bq][2*h+1]);
                        mma_bf16(acc[mt][nt], Al[mt], Bh[bq][2*h], Bh[bq][2*h+1]);
                    }
                }
            }
        }
        __syncthreads();
    }

    const int g = lane >> 2;
    const int t = lane & 3;
    const int bidx = n0 / P;
    const int pofs = n0 % P;
#pragma unroll
    for (int mt = 0; mt < 2; mt++) {
        int mrow = m0 + wm * 32 + mt * 16 + g;
        float* r0 = out + ((size_t)(bidx * COUT + mrow)) * P + pofs;
        float* r1 = r0 + 8 * P;
#pragma unroll
        for (int nt = 0; nt < 4; nt++) {
            int col = wn * 32 + nt * 8 + 2 * t;
            *(float2*)(r0 + col) = make_float2(acc[mt][nt][0], acc[mt][nt][1]);
            *(float2*)(r1 + col) = make_float2(acc[mt][nt][2], acc[mt][nt][3]);
        }
    }
}

// ---------------------------------------------------------------------------
extern "C" void kernel_launch(void* const* d_in, const int* in_sizes, int n_in,
                              void* d_out, int out_size)
{
    const float* x     = (const float*)d_in[0];
    const float* wgt   = (const float*)d_in[1];
    const float* off_w = (const float*)d_in[2];
    const float* off_b = (const float*)d_in[3];
    float* out = (float*)d_out;

    cudaFuncSetAttribute(gemm_mma_kernel, cudaFuncAttributeMaxDynamicSharedMemorySize, SMEM_TOTAL);

    wconv_kernel<<<(COUT * KDIM + 255) / 256, 256>>>(wgt);

    dim3 g1((STRIPS + 255) / 256, NCHUNK);
    offconv_kernel<<<g1, 256>>>(x, off_w, off_b);

    dim3 g2((P + 255) / 256, BB, KK9);
    sample_kernel<<<g2, 256>>>(x);

    dim3 g3(NTOT / BN, COUT / BM);
    gemm_mma_kernel<<<g3, 256, SMEM_TOTAL>>>(out);
}